// round 17
// baseline (speedup 1.0000x reference)
#include <cuda_runtime.h>

#define N_NODES 100000
#define N_EDGES 3200000
#define IN_DIM 64
#define HID_DIM 128
#define OUT_DIM 2
#define IN_VEC (IN_DIM / 4)       // 16 float4 per node row
#define HID_VEC (HID_DIM / 4)     // 32

#define SCAN_CHUNK 1024
#define N_SCAN_BLOCKS ((N_NODES + SCAN_CHUNK - 1) / SCAN_CHUNK)   // 98

#define NODES_PER_BLK 16
#define FUSE_BLOCKS ((N_NODES + NODES_PER_BLK - 1) / NODES_PER_BLK)  // 6250
#define SA_STRIDE 68              // floats per node row in smem (bank offset pad)

// Scratch (device globals: allocation-free rule)
__device__ __align__(16) int    g_cnt[N_NODES];
__device__ __align__(16) int    g_start[N_NODES];
__device__ __align__(16) int    g_cur[N_NODES];
__device__ __align__(16) float  g_dinv[N_NODES];
__device__ __align__(16) int    g_bsum[N_SCAN_BLOCKS];
__device__ __align__(16) float2 g_entry[N_EDGES];          // {src bits, norm} 25.6 MB

// ---------------------------------------------------------------------------
__global__ void k_zero() {
    int i = blockIdx.x * blockDim.x + threadIdx.x;
    if (i < N_NODES) g_cnt[i] = 0;
}

// In-degree histogram (int reductions)
__global__ void k_count(const int* __restrict__ ei) {
    int i = blockIdx.x * blockDim.x + threadIdx.x;
    if (i < N_EDGES) {
        int d = ei[N_EDGES + i];
        if ((unsigned)d < N_NODES) atomicAdd(&g_cnt[d], 1);
    }
}

// Scan pass 1: per-block (1024 elems) exclusive scan of g_cnt into g_start,
// block totals to g_bsum. Also dinv = rsqrt(cnt+1) (self-loop incl).
__global__ __launch_bounds__(256)
void k_scan1() {
    __shared__ int s_sum[256];
    int b = blockIdx.x, t = threadIdx.x;
    int base = b * SCAN_CHUNK + t * 4;

    int c0 = 0, c1 = 0, c2 = 0, c3 = 0;
    if (base + 3 < N_NODES) {
        int4 c = *(const int4*)&g_cnt[base];
        c0 = c.x; c1 = c.y; c2 = c.z; c3 = c.w;
    } else {
        if (base + 0 < N_NODES) c0 = g_cnt[base + 0];
        if (base + 1 < N_NODES) c1 = g_cnt[base + 1];
        if (base + 2 < N_NODES) c2 = g_cnt[base + 2];
    }
    int s0 = c0, s1 = s0 + c1, s2 = s1 + c2, s3 = s2 + c3;
    s_sum[t] = s3;
    __syncthreads();
#pragma unroll
    for (int off = 1; off < 256; off <<= 1) {
        int v = 0;
        if (t >= off) v = s_sum[t - off];
        __syncthreads();
        if (t >= off) s_sum[t] += v;
        __syncthreads();
    }
    int excl = (t > 0) ? s_sum[t - 1] : 0;
    if (base + 0 < N_NODES) { g_start[base + 0] = excl;       g_dinv[base + 0] = rsqrtf((float)c0 + 1.0f); }
    if (base + 1 < N_NODES) { g_start[base + 1] = excl + s0;  g_dinv[base + 1] = rsqrtf((float)c1 + 1.0f); }
    if (base + 2 < N_NODES) { g_start[base + 2] = excl + s1;  g_dinv[base + 2] = rsqrtf((float)c2 + 1.0f); }
    if (base + 3 < N_NODES) { g_start[base + 3] = excl + s2;  g_dinv[base + 3] = rsqrtf((float)c3 + 1.0f); }
    if (t == 255) g_bsum[b] = s_sum[255];
}

// Scan pass 2: exclusive scan of the 98 block sums (single block)
__global__ __launch_bounds__(128)
void k_scan2() {
    __shared__ int s[128];
    int t = threadIdx.x;
    s[t] = (t < N_SCAN_BLOCKS) ? g_bsum[t] : 0;
    __syncthreads();
#pragma unroll
    for (int off = 1; off < 128; off <<= 1) {
        int v = 0;
        if (t >= off) v = s[t - off];
        __syncthreads();
        if (t >= off) s[t] += v;
        __syncthreads();
    }
    if (t < N_SCAN_BLOCKS) g_bsum[t] = (t > 0) ? s[t - 1] : 0;
}

// Scan pass 3: add block offsets; init write cursors
__global__ void k_scan3() {
    int i = blockIdx.x * blockDim.x + threadIdx.x;
    if (i < N_NODES) {
        int v = g_start[i] + g_bsum[i >> 10];
        g_start[i] = v;
        g_cur[i] = v;
    }
}

// Counting-sort fill: per-dst edge lists of packed {src, norm}
__global__ void k_scatter(const int* __restrict__ ei) {
    int i = blockIdx.x * blockDim.x + threadIdx.x;
    if (i < N_EDGES) {
        int s = ei[i];
        int t = ei[N_EDGES + i];
        if ((unsigned)s >= N_NODES || (unsigned)t >= N_NODES) return;
        float norm = g_dinv[s] * g_dinv[t];
        int slot = atomicAdd(&g_cur[t], 1);
        if ((unsigned)slot < N_EDGES)                 // clamp: corrupt -> wrong, not hang
            g_entry[slot] = make_float2(__int_as_float(s), norm);
    }
}

// ---------------------------------------------------------------------------
// FUSED aggregate + head. 256 threads / 16 nodes per block.
// Phase 1 (16 thr/node): CSR gather-accumulate agg row into smem (R8 logic).
// Phase 2 (16 thr/node): hid = relu(agg @ Wg + bg); out = hid @ Wl + bl,
//   each thread owns 8 hidden cols, shfl-reduce the 2 outputs.
// Memory-bound phase 1 of some CTAs overlaps FMA-bound phase 2 of others.
__global__ __launch_bounds__(256)
void k_fused(const float4* __restrict__ x4,
             const float4* __restrict__ Wg4,
             const float* __restrict__ bg,
             const float* __restrict__ Wl,
             const float* __restrict__ bl,
             float2* __restrict__ out) {
    __shared__ float4 sW[IN_DIM * HID_VEC];             // 32 KB [k][jq]
    __shared__ float  sA[NODES_PER_BLK * SA_STRIDE];    // 4.25 KB agg rows
    __shared__ float  sWl[HID_DIM * 2];
    __shared__ float  sbg[HID_DIM];

    int tid = threadIdx.x;
    for (int i = tid; i < IN_DIM * HID_VEC; i += 256) sW[i] = Wg4[i];
    for (int i = tid; i < HID_DIM * 2; i += 256) sWl[i] = Wl[i];
    for (int i = tid; i < HID_DIM; i += 256) sbg[i] = bg[i];

    int nl   = tid >> 4;          // node-local 0..15
    int lane = tid & 15;          // float4 column 0..15
    int node = blockIdx.x * NODES_PER_BLK + nl;
    bool live = (node < N_NODES);

    // ---- Phase 1: aggregate (exact R8 inner loop) ----
    float4 acc = make_float4(0.f, 0.f, 0.f, 0.f);
    if (live) {
        float di = g_dinv[node];
        float sl = di * di;
        float4 v = x4[node * IN_VEC + lane];
        acc.x = v.x * sl; acc.y = v.y * sl; acc.z = v.z * sl; acc.w = v.w * sl;

        int j = g_start[node];
        if (j < 0) j = 0;
        int cnt = g_cnt[node];
        if (cnt < 0) cnt = 0;
        long long e64 = (long long)j + cnt;
        int end = (e64 > N_EDGES) ? N_EDGES : (int)e64;

        for (; j + 1 < end; j += 2) {
            float2 en0 = g_entry[j];
            float2 en1 = g_entry[j + 1];
            int s0 = __float_as_int(en0.x);
            int s1 = __float_as_int(en1.x);
            if ((unsigned)s0 < N_NODES) {
                float4 w = __ldg(&x4[s0 * IN_VEC + lane]);
                acc.x = fmaf(w.x, en0.y, acc.x);
                acc.y = fmaf(w.y, en0.y, acc.y);
                acc.z = fmaf(w.z, en0.y, acc.z);
                acc.w = fmaf(w.w, en0.y, acc.w);
            }
            if ((unsigned)s1 < N_NODES) {
                float4 w = __ldg(&x4[s1 * IN_VEC + lane]);
                acc.x = fmaf(w.x, en1.y, acc.x);
                acc.y = fmaf(w.y, en1.y, acc.y);
                acc.z = fmaf(w.z, en1.y, acc.z);
                acc.w = fmaf(w.w, en1.y, acc.w);
            }
        }
        if (j < end) {
            float2 en = g_entry[j];
            int s0 = __float_as_int(en.x);
            if ((unsigned)s0 < N_NODES) {
                float4 w = __ldg(&x4[s0 * IN_VEC + lane]);
                acc.x = fmaf(w.x, en.y, acc.x);
                acc.y = fmaf(w.y, en.y, acc.y);
                acc.z = fmaf(w.z, en.y, acc.z);
                acc.w = fmaf(w.w, en.y, acc.w);
            }
        }
    }
    // stash agg row in smem (padded stride: conflict-free phase-2 reads)
    {
        float* row = &sA[nl * SA_STRIDE + lane * 4];
        row[0] = acc.x; row[1] = acc.y; row[2] = acc.z; row[3] = acc.w;
    }
    __syncthreads();

    // ---- Phase 2: head. Thread owns hidden cols [lane*8, lane*8+8). ----
    {
        int q0 = lane * 2;                       // first owned jq quad
        float4 h0 = make_float4(sbg[q0*4+0], sbg[q0*4+1], sbg[q0*4+2], sbg[q0*4+3]);
        float4 h1 = make_float4(sbg[q0*4+4], sbg[q0*4+5], sbg[q0*4+6], sbg[q0*4+7]);
        const float* arow = &sA[nl * SA_STRIDE];
#pragma unroll
        for (int k = 0; k < IN_DIM; k++) {
            float ak = arow[k];                  // broadcast within node group
            float4 w0 = sW[k * HID_VEC + q0];
            float4 w1 = sW[k * HID_VEC + q0 + 1];
            h0.x = fmaf(ak, w0.x, h0.x); h0.y = fmaf(ak, w0.y, h0.y);
            h0.z = fmaf(ak, w0.z, h0.z); h0.w = fmaf(ak, w0.w, h0.w);
            h1.x = fmaf(ak, w1.x, h1.x); h1.y = fmaf(ak, w1.y, h1.y);
            h1.z = fmaf(ak, w1.z, h1.z); h1.w = fmaf(ak, w1.w, h1.w);
        }
        h0.x = fmaxf(h0.x, 0.f); h0.y = fmaxf(h0.y, 0.f);
        h0.z = fmaxf(h0.z, 0.f); h0.w = fmaxf(h0.w, 0.f);
        h1.x = fmaxf(h1.x, 0.f); h1.y = fmaxf(h1.y, 0.f);
        h1.z = fmaxf(h1.z, 0.f); h1.w = fmaxf(h1.w, 0.f);

        int j0 = lane * 8;
        float o0 = 0.f, o1 = 0.f;
        o0 = fmaf(h0.x, sWl[2*(j0+0)+0], o0); o1 = fmaf(h0.x, sWl[2*(j0+0)+1], o1);
        o0 = fmaf(h0.y, sWl[2*(j0+1)+0], o0); o1 = fmaf(h0.y, sWl[2*(j0+1)+1], o1);
        o0 = fmaf(h0.z, sWl[2*(j0+2)+0], o0); o1 = fmaf(h0.z, sWl[2*(j0+2)+1], o1);
        o0 = fmaf(h0.w, sWl[2*(j0+3)+0], o0); o1 = fmaf(h0.w, sWl[2*(j0+3)+1], o1);
        o0 = fmaf(h1.x, sWl[2*(j0+4)+0], o0); o1 = fmaf(h1.x, sWl[2*(j0+4)+1], o1);
        o0 = fmaf(h1.y, sWl[2*(j0+5)+0], o0); o1 = fmaf(h1.y, sWl[2*(j0+5)+1], o1);
        o0 = fmaf(h1.z, sWl[2*(j0+6)+0], o0); o1 = fmaf(h1.z, sWl[2*(j0+6)+1], o1);
        o0 = fmaf(h1.w, sWl[2*(j0+7)+0], o0); o1 = fmaf(h1.w, sWl[2*(j0+7)+1], o1);

        // reduce across the 16 lanes of this node
#pragma unroll
        for (int m = 8; m >= 1; m >>= 1) {
            o0 += __shfl_xor_sync(0xffffffffu, o0, m, 16);
            o1 += __shfl_xor_sync(0xffffffffu, o1, m, 16);
        }
        if (lane == 0 && live) out[node] = make_float2(o0 + bl[0], o1 + bl[1]);
    }
}

// ---------------------------------------------------------------------------
extern "C" void kernel_launch(void* const* d_in, const int* in_sizes, int n_in,
                              void* d_out, int out_size) {
    const float* x  = (const float*)d_in[0];
    const int*   ei = (const int*)d_in[1];     // int32 (JAX default x64 off)
    const float* Wg = (const float*)d_in[2];
    const float* bg = (const float*)d_in[3];
    const float* Wl = (const float*)d_in[4];
    const float* bl = (const float*)d_in[5];
    float2*      out = (float2*)d_out;

    const float4* x4  = (const float4*)x;
    const float4* Wg4 = (const float4*)Wg;

    k_zero   <<<(N_NODES + 255) / 256, 256>>>();
    k_count  <<<(N_EDGES + 255) / 256, 256>>>(ei);
    k_scan1  <<<N_SCAN_BLOCKS, 256>>>();
    k_scan2  <<<1, 128>>>();
    k_scan3  <<<(N_NODES + 255) / 256, 256>>>();
    k_scatter<<<(N_EDGES + 255) / 256, 256>>>(ei);
    k_fused  <<<FUSE_BLOCKS, 256>>>(x4, Wg4, bg, Wl, bl, out);
}